// round 1
// baseline (speedup 1.0000x reference)
#include <cuda_runtime.h>

// SAXS pair-distance P(r) L1 loss.
// Strategy:
//  - Pack (x,y,z,mask) into float4 arrays for both structures (prepack kernel,
//    also zeroes the global histograms).
//  - Tiled O(N^2/2) pair kernel: 128x128 atom tiles, 256 threads, each thread
//    owns an 8x8 register sub-tile. Soft linear binning always touches two
//    ADJACENT bins (lo, lo+1), so we accumulate fixed-point u32 counts and do
//    ONE 64-bit shared-memory atomicAdd per pair using two parity-offset
//    histogram arrays (even lo -> hA[lo] 8B-aligned; odd lo -> hB[lo+1]).
//  - Per-block shared histograms flushed with u32 global atomics (deterministic).
//  - Single-block finalize: normalize both histograms (scale cancels) and
//    compute sum|p-q| in fp64.

namespace {
constexpr int kNBins     = 201;          // DMAX/STEP + 1
constexpr int kNAtoms    = 9472;         // 256*37
constexpr int kTile      = 128;
constexpr int kNTiles    = kNAtoms / kTile;                  // 74 (exact)
constexpr int kNPairTiles = kNTiles * (kNTiles + 1) / 2;     // 2775
constexpr unsigned kScale = 512u;        // fixed-point scale for soft-bin weights
}

__device__ float4       g_pos[2][kNAtoms];   // (x,y,z,mask), [0]=pred, [1]=true
__device__ unsigned int g_hist[2][256];      // fixed-point histograms (201 used)

// ---------------------------------------------------------------------------
__global__ void prepack_kernel(const float* __restrict__ pred,
                               const float* __restrict__ tru,
                               const float* __restrict__ mask) {
    int i = blockIdx.x * blockDim.x + threadIdx.x;
    if (i < 512) ((unsigned int*)g_hist)[i] = 0u;   // zero both histograms
    if (i < kNAtoms) {
        float m = mask[i];
        g_pos[0][i] = make_float4(pred[3*i + 0], pred[3*i + 1], pred[3*i + 2], m);
        g_pos[1][i] = make_float4(tru [3*i + 0], tru [3*i + 1], tru [3*i + 2], m);
    }
}

// ---------------------------------------------------------------------------
__global__ __launch_bounds__(256, 2)
void pair_hist_kernel() {
    __shared__ float4 ti[kTile];
    __shared__ float4 tj[kTile];
    __shared__ __align__(8) unsigned int hA[204];  // bin k at index k    (even lo)
    __shared__ __align__(8) unsigned int hB[204];  // bin k at index k+1  (odd  lo)

    const int s = blockIdx.y;          // 0 = pred, 1 = true
    const int p = blockIdx.x;          // linear upper-triangle tile index

    // Decode p -> (bi, bj) with bi <= bj (row-major upper triangle incl. diag).
    double Td = (double)kNTiles;
    int bi = (int)(((2.0 * Td + 1.0) -
                    sqrt((2.0 * Td + 1.0) * (2.0 * Td + 1.0) - 8.0 * (double)p)) * 0.5);
    if (bi < 0) bi = 0;
    if (bi > kNTiles - 1) bi = kNTiles - 1;
    while (bi * (2 * kNTiles - bi + 1) / 2 > p) --bi;
    while ((bi + 1) * (2 * kNTiles - bi) / 2 <= p) ++bi;
    const int bj = bi + (p - bi * (2 * kNTiles - bi + 1) / 2);

    const int tid = threadIdx.x;
    if (tid < kTile) ti[tid]         = g_pos[s][bi * kTile + tid];
    else             tj[tid - kTile] = g_pos[s][bj * kTile + (tid - kTile)];
    for (int k = tid; k < 204; k += 256) { hA[k] = 0u; hB[k] = 0u; }
    __syncthreads();

    const int tx = tid & 15;   // 16 x 16 thread grid over the 128x128 tile
    const int ty = tid >> 4;

    float4 ri[8], rj[8];
#pragma unroll
    for (int u = 0; u < 8; ++u) ri[u] = ti[ty * 8 + u];
#pragma unroll
    for (int v = 0; v < 8; ++v) rj[v] = tj[tx * 8 + v];

    const bool diag = (bi == bj);

#pragma unroll
    for (int u = 0; u < 8; ++u) {
#pragma unroll
        for (int v = 0; v < 8; ++v) {
            float dx = ri[u].x - rj[v].x;
            float dy = ri[u].y - rj[v].y;
            float dz = ri[u].z - rj[v].z;
            float d2 = fmaf(dx, dx, fmaf(dy, dy, dz * dz));
            d2 = fmaxf(d2, 1e-12f);                 // matches reference clamp
            float d = d2 * rsqrtf(d2);              // one MUFU per pair
            float t = fminf(d * 2.0f, 200.0f);      // d / STEP, clipped
            int   lo   = (int)t;                    // floor (t >= 0)
            float frac = t - (float)lo;
            unsigned q = __float2uint_rn(frac * (float)kScale);
            float w = ri[u].w * rj[v].w;
            // strict upper triangle on the diagonal tile; mask gate
            bool ok = (w != 0.0f) && (!diag || ((ty * 8 + u) < (tx * 8 + v)));
            if (ok) {
                // little-endian: low word -> bin lo, high word -> bin lo+1
                unsigned long long val =
                    ((unsigned long long)q << 32) | (unsigned long long)(kScale - q);
                if (lo & 1) atomicAdd((unsigned long long*)(hB + lo + 1), val);
                else        atomicAdd((unsigned long long*)(hA + lo),     val);
            }
        }
    }

    __syncthreads();
    if (tid < kNBins) {
        unsigned v = hA[tid] + hB[tid + 1];
        if (v) atomicAdd(&g_hist[s][tid], v);
    }
}

// ---------------------------------------------------------------------------
__global__ void finalize_kernel(float* __restrict__ out) {
    __shared__ double sh[256];
    int tid = threadIdx.x;
    double h0 = (tid < kNBins) ? (double)g_hist[0][tid] : 0.0;
    double h1 = (tid < kNBins) ? (double)g_hist[1][tid] : 0.0;

    sh[tid] = h0; __syncthreads();
    for (int o = 128; o > 0; o >>= 1) { if (tid < o) sh[tid] += sh[tid + o]; __syncthreads(); }
    double s0 = sh[0]; __syncthreads();

    sh[tid] = h1; __syncthreads();
    for (int o = 128; o > 0; o >>= 1) { if (tid < o) sh[tid] += sh[tid + o]; __syncthreads(); }
    double s1 = sh[0]; __syncthreads();

    double l = fabs(h0 / (s0 + 1e-12) - h1 / (s1 + 1e-12));
    sh[tid] = l; __syncthreads();
    for (int o = 128; o > 0; o >>= 1) { if (tid < o) sh[tid] += sh[tid + o]; __syncthreads(); }

    if (tid == 0) out[0] = (float)sh[0];
}

// ---------------------------------------------------------------------------
extern "C" void kernel_launch(void* const* d_in, const int* in_sizes, int n_in,
                              void* d_out, int out_size) {
    (void)in_sizes; (void)n_in; (void)out_size;
    const float* pred = (const float*)d_in[0];
    const float* tru  = (const float*)d_in[1];
    const float* mask = (const float*)d_in[2];

    prepack_kernel<<<(kNAtoms + 255) / 256, 256>>>(pred, tru, mask);

    dim3 grid(kNPairTiles, 2);
    pair_hist_kernel<<<grid, 256>>>();

    finalize_kernel<<<1, 256>>>((float*)d_out);
}

// round 2
// speedup vs baseline: 1.7204x; 1.7204x over previous
#include <cuda_runtime.h>

// SAXS pair-distance P(r) L1 loss — Round 2.
// Change vs R1: replace smem 64-bit atomics (measured bound: 2 cyc/lane ATOMS)
// with global RED.E.ADD.64 into a 128x-replicated L2-resident histogram
// (REDG spread = 1.29 cyc/lane). Parity-packed adjacent-bin trick retained:
// soft linear binning always hits bins (lo, lo+1), so one u64 add carries both
// fixed-point u32 counts via two parity-offset arrays (even lo -> A[lo],
// odd lo -> B[lo+1]; both 8B-aligned).
// Also: coords prescaled by 1024 (=512/STEP) so t*512 comes straight out of
// rsqrt; single F2I; masked atoms displaced into a discard bin (no per-pair
// mask math); diagonal predicate only on diagonal tiles.

namespace {
constexpr int   kNBins      = 201;                       // DMAX/STEP + 1
constexpr int   kNAtoms     = 9472;                      // 256*37
constexpr int   kTile       = 128;
constexpr int   kNTiles     = kNAtoms / kTile;           // 74 (exact)
constexpr int   kNPairTiles = kNTiles * (kNTiles + 1) / 2;  // 2775
constexpr int   kReps       = 128;                       // histogram replicas
constexpr float kPre        = 1024.0f;                   // 512 / STEP
constexpr float kClampT512  = 103418.0f;                 // ~201.99 * 512 (discard >=201)
}

struct Rep {
    unsigned int A[256];   // bin k (even lo): pair written at A[lo], A[lo+1]
    unsigned int B[256];   // bin k (odd  lo): pair written at B[lo+1], B[lo+2]
};

__device__ float4 g_pos[2][kNAtoms];   // prescaled (x,y,z,-), [0]=pred, [1]=true
__device__ Rep    g_rep[2][kReps];     // 512 KB, L2-resident

// ---------------------------------------------------------------------------
__global__ void zero_kernel() {
    // 2 * 128 * 512 u32 = 131072 u32 = 32768 uint4
    uint4* p = (uint4*)g_rep;
    int i = blockIdx.x * blockDim.x + threadIdx.x;
    p[i] = make_uint4(0u, 0u, 0u, 0u);
}

// ---------------------------------------------------------------------------
__global__ void prepack_kernel(const float* __restrict__ pred,
                               const float* __restrict__ tru,
                               const float* __restrict__ mask) {
    int i = blockIdx.x * blockDim.x + threadIdx.x;
    if (i >= kNAtoms) return;
    float m = mask[i];
    if (m != 0.0f) {
        g_pos[0][i] = make_float4(pred[3*i+0]*kPre, pred[3*i+1]*kPre, pred[3*i+2]*kPre, 0.f);
        g_pos[1][i] = make_float4(tru [3*i+0]*kPre, tru [3*i+1]*kPre, tru [3*i+2]*kPre, 0.f);
    } else {
        // Displace masked atoms so every pair involving them lands beyond the
        // t clamp -> lo=201 -> discard bins. Pairwise masked-masked separation
        // >= 2e5 (scaled) >> 103424; masked-valid separation ~1e8.
        float dx = 1.0e8f + (float)i * 2.0e5f;
        g_pos[0][i] = make_float4(dx, 0.f, 0.f, 0.f);
        g_pos[1][i] = make_float4(dx, 0.f, 0.f, 0.f);
    }
}

// ---------------------------------------------------------------------------
__global__ __launch_bounds__(256, 3)
void pair_hist_kernel() {
    __shared__ float4 ti[kTile];
    __shared__ float4 tj[kTile];

    const int s = blockIdx.y;          // 0 = pred, 1 = true
    const int p = blockIdx.x;          // linear upper-triangle tile index

    // Decode p -> (bi, bj), bi <= bj (row-major upper triangle incl. diagonal).
    double Td = (double)kNTiles;
    int bi = (int)(((2.0 * Td + 1.0) -
                    sqrt((2.0 * Td + 1.0) * (2.0 * Td + 1.0) - 8.0 * (double)p)) * 0.5);
    if (bi < 0) bi = 0;
    if (bi > kNTiles - 1) bi = kNTiles - 1;
    while (bi * (2 * kNTiles - bi + 1) / 2 > p) --bi;
    while ((bi + 1) * (2 * kNTiles - bi) / 2 <= p) ++bi;
    const int bj = bi + (p - bi * (2 * kNTiles - bi + 1) / 2);

    const int tid = threadIdx.x;
    if (tid < kTile) ti[tid]         = g_pos[s][bi * kTile + tid];
    else             tj[tid - kTile] = g_pos[s][bj * kTile + (tid - kTile)];
    __syncthreads();

    unsigned int* __restrict__ baseA = g_rep[s][p & (kReps - 1)].A;
    unsigned int* __restrict__ baseB = g_rep[s][p & (kReps - 1)].B;

    const int tx = tid & 15;           // 16x16 thread grid over 128x128 tile
    const int ty = tid >> 4;

    float3 ri[8], rj[8];
#pragma unroll
    for (int u = 0; u < 8; ++u) {
        float4 a = ti[ty * 8 + u];
        ri[u] = make_float3(a.x, a.y, a.z);
    }
#pragma unroll
    for (int v = 0; v < 8; ++v) {
        float4 b = tj[tx * 8 + v];
        rj[v] = make_float3(b.x, b.y, b.z);
    }

    if (bi != bj) {
#pragma unroll
        for (int u = 0; u < 8; ++u) {
#pragma unroll
            for (int v = 0; v < 8; ++v) {
                float dx = ri[u].x - rj[v].x;
                float dy = ri[u].y - rj[v].y;
                float dz = ri[u].z - rj[v].z;
                float d2 = fmaf(dx, dx, fmaf(dy, dy, dz * dz));
                d2 = fmaxf(d2, 1.0486e-6f);              // 1e-12 * 1024^2
                float t = fminf(d2 * rsqrtf(d2), kClampT512);   // = d*512/STEP
                int it = (int)t;
                int lo = it >> 9;
                unsigned q = (unsigned)(it & 511);
                unsigned long long val =
                    ((unsigned long long)q << 32) | (unsigned long long)(512u - q);
                unsigned int* addr = (lo & 1) ? (baseB + lo + 1) : (baseA + lo);
                atomicAdd((unsigned long long*)addr, val);  // -> RED.E.ADD.64
            }
        }
    } else {
#pragma unroll
        for (int u = 0; u < 8; ++u) {
            const int iu = ty * 8 + u;
#pragma unroll
            for (int v = 0; v < 8; ++v) {
                const int jv = tx * 8 + v;
                float dx = ri[u].x - rj[v].x;
                float dy = ri[u].y - rj[v].y;
                float dz = ri[u].z - rj[v].z;
                float d2 = fmaf(dx, dx, fmaf(dy, dy, dz * dz));
                d2 = fmaxf(d2, 1.0486e-6f);
                float t = fminf(d2 * rsqrtf(d2), kClampT512);
                int it = (int)t;
                int lo = it >> 9;
                unsigned q = (unsigned)(it & 511);
                unsigned long long val =
                    ((unsigned long long)q << 32) | (unsigned long long)(512u - q);
                unsigned int* addr = (lo & 1) ? (baseB + lo + 1) : (baseA + lo);
                if (iu < jv)                                 // strict upper triangle
                    atomicAdd((unsigned long long*)addr, val);
            }
        }
    }
}

// ---------------------------------------------------------------------------
__global__ void finalize_kernel(float* __restrict__ out) {
    __shared__ double sh[256];
    const int tid = threadIdx.x;

    double h0 = 0.0, h1 = 0.0;
    if (tid < kNBins) {
        unsigned long long a0 = 0ull, a1 = 0ull;
#pragma unroll 8
        for (int r = 0; r < kReps; ++r) {
            a0 += (unsigned long long)g_rep[0][r].A[tid]
                + (unsigned long long)g_rep[0][r].B[tid + 1];
            a1 += (unsigned long long)g_rep[1][r].A[tid]
                + (unsigned long long)g_rep[1][r].B[tid + 1];
        }
        h0 = (double)a0;
        h1 = (double)a1;
    }

    sh[tid] = h0; __syncthreads();
    for (int o = 128; o > 0; o >>= 1) { if (tid < o) sh[tid] += sh[tid + o]; __syncthreads(); }
    double s0 = sh[0]; __syncthreads();

    sh[tid] = h1; __syncthreads();
    for (int o = 128; o > 0; o >>= 1) { if (tid < o) sh[tid] += sh[tid + o]; __syncthreads(); }
    double s1 = sh[0]; __syncthreads();

    double l = fabs(h0 / (s0 + 1e-12) - h1 / (s1 + 1e-12));
    sh[tid] = l; __syncthreads();
    for (int o = 128; o > 0; o >>= 1) { if (tid < o) sh[tid] += sh[tid + o]; __syncthreads(); }

    if (tid == 0) out[0] = (float)sh[0];
}

// ---------------------------------------------------------------------------
extern "C" void kernel_launch(void* const* d_in, const int* in_sizes, int n_in,
                              void* d_out, int out_size) {
    (void)in_sizes; (void)n_in; (void)out_size;
    const float* pred = (const float*)d_in[0];
    const float* tru  = (const float*)d_in[1];
    const float* mask = (const float*)d_in[2];

    zero_kernel<<<128, 256>>>();
    prepack_kernel<<<(kNAtoms + 255) / 256, 256>>>(pred, tru, mask);

    dim3 grid(kNPairTiles, 2);
    pair_hist_kernel<<<grid, 256>>>();

    finalize_kernel<<<1, 256>>>((float*)d_out);
}

// round 3
// speedup vs baseline: 1.7245x; 1.0024x over previous
#include <cuda_runtime.h>

// SAXS pair-distance P(r) L1 loss — Round 2.
// Change vs R1: replace smem 64-bit atomics (measured bound: 2 cyc/lane ATOMS)
// with global RED.E.ADD.64 into a 128x-replicated L2-resident histogram
// (REDG spread = 1.29 cyc/lane). Parity-packed adjacent-bin trick retained:
// soft linear binning always hits bins (lo, lo+1), so one u64 add carries both
// fixed-point u32 counts via two parity-offset arrays (even lo -> A[lo],
// odd lo -> B[lo+1]; both 8B-aligned).
// Also: coords prescaled by 1024 (=512/STEP) so t*512 comes straight out of
// rsqrt; single F2I; masked atoms displaced into a discard bin (no per-pair
// mask math); diagonal predicate only on diagonal tiles.

namespace {
constexpr int   kNBins      = 201;                       // DMAX/STEP + 1
constexpr int   kNAtoms     = 9472;                      // 256*37
constexpr int   kTile       = 128;
constexpr int   kNTiles     = kNAtoms / kTile;           // 74 (exact)
constexpr int   kNPairTiles = kNTiles * (kNTiles + 1) / 2;  // 2775
constexpr int   kReps       = 128;                       // histogram replicas
constexpr float kPre        = 1024.0f;                   // 512 / STEP
constexpr float kClampT512  = 103418.0f;                 // ~201.99 * 512 (discard >=201)
}

struct Rep {
    unsigned int A[256];   // bin k (even lo): pair written at A[lo], A[lo+1]
    unsigned int B[256];   // bin k (odd  lo): pair written at B[lo+1], B[lo+2]
};

__device__ float4 g_pos[2][kNAtoms];   // prescaled (x,y,z,-), [0]=pred, [1]=true
__device__ Rep    g_rep[2][kReps];     // 512 KB, L2-resident

// ---------------------------------------------------------------------------
__global__ void zero_kernel() {
    // 2 * 128 * 512 u32 = 131072 u32 = 32768 uint4
    uint4* p = (uint4*)g_rep;
    int i = blockIdx.x * blockDim.x + threadIdx.x;
    p[i] = make_uint4(0u, 0u, 0u, 0u);
}

// ---------------------------------------------------------------------------
__global__ void prepack_kernel(const float* __restrict__ pred,
                               const float* __restrict__ tru,
                               const float* __restrict__ mask) {
    int i = blockIdx.x * blockDim.x + threadIdx.x;
    if (i >= kNAtoms) return;
    float m = mask[i];
    if (m != 0.0f) {
        g_pos[0][i] = make_float4(pred[3*i+0]*kPre, pred[3*i+1]*kPre, pred[3*i+2]*kPre, 0.f);
        g_pos[1][i] = make_float4(tru [3*i+0]*kPre, tru [3*i+1]*kPre, tru [3*i+2]*kPre, 0.f);
    } else {
        // Displace masked atoms so every pair involving them lands beyond the
        // t clamp -> lo=201 -> discard bins. Pairwise masked-masked separation
        // >= 2e5 (scaled) >> 103424; masked-valid separation ~1e8.
        float dx = 1.0e8f + (float)i * 2.0e5f;
        g_pos[0][i] = make_float4(dx, 0.f, 0.f, 0.f);
        g_pos[1][i] = make_float4(dx, 0.f, 0.f, 0.f);
    }
}

// ---------------------------------------------------------------------------
__global__ __launch_bounds__(256, 3)
void pair_hist_kernel() {
    __shared__ float4 ti[kTile];
    __shared__ float4 tj[kTile];

    const int s = blockIdx.y;          // 0 = pred, 1 = true
    const int p = blockIdx.x;          // linear upper-triangle tile index

    // Decode p -> (bi, bj), bi <= bj (row-major upper triangle incl. diagonal).
    double Td = (double)kNTiles;
    int bi = (int)(((2.0 * Td + 1.0) -
                    sqrt((2.0 * Td + 1.0) * (2.0 * Td + 1.0) - 8.0 * (double)p)) * 0.5);
    if (bi < 0) bi = 0;
    if (bi > kNTiles - 1) bi = kNTiles - 1;
    while (bi * (2 * kNTiles - bi + 1) / 2 > p) --bi;
    while ((bi + 1) * (2 * kNTiles - bi) / 2 <= p) ++bi;
    const int bj = bi + (p - bi * (2 * kNTiles - bi + 1) / 2);

    const int tid = threadIdx.x;
    if (tid < kTile) ti[tid]         = g_pos[s][bi * kTile + tid];
    else             tj[tid - kTile] = g_pos[s][bj * kTile + (tid - kTile)];
    __syncthreads();

    unsigned int* __restrict__ baseA = g_rep[s][p & (kReps - 1)].A;
    unsigned int* __restrict__ baseB = g_rep[s][p & (kReps - 1)].B;

    const int tx = tid & 15;           // 16x16 thread grid over 128x128 tile
    const int ty = tid >> 4;

    float3 ri[8], rj[8];
#pragma unroll
    for (int u = 0; u < 8; ++u) {
        float4 a = ti[ty * 8 + u];
        ri[u] = make_float3(a.x, a.y, a.z);
    }
#pragma unroll
    for (int v = 0; v < 8; ++v) {
        float4 b = tj[tx * 8 + v];
        rj[v] = make_float3(b.x, b.y, b.z);
    }

    if (bi != bj) {
#pragma unroll
        for (int u = 0; u < 8; ++u) {
#pragma unroll
            for (int v = 0; v < 8; ++v) {
                float dx = ri[u].x - rj[v].x;
                float dy = ri[u].y - rj[v].y;
                float dz = ri[u].z - rj[v].z;
                float d2 = fmaf(dx, dx, fmaf(dy, dy, dz * dz));
                d2 = fmaxf(d2, 1.0486e-6f);              // 1e-12 * 1024^2
                float t = fminf(d2 * rsqrtf(d2), kClampT512);   // = d*512/STEP
                int it = (int)t;
                int lo = it >> 9;
                unsigned q = (unsigned)(it & 511);
                unsigned long long val =
                    ((unsigned long long)q << 32) | (unsigned long long)(512u - q);
                unsigned int* addr = (lo & 1) ? (baseB + lo + 1) : (baseA + lo);
                atomicAdd((unsigned long long*)addr, val);  // -> RED.E.ADD.64
            }
        }
    } else {
#pragma unroll
        for (int u = 0; u < 8; ++u) {
            const int iu = ty * 8 + u;
#pragma unroll
            for (int v = 0; v < 8; ++v) {
                const int jv = tx * 8 + v;
                float dx = ri[u].x - rj[v].x;
                float dy = ri[u].y - rj[v].y;
                float dz = ri[u].z - rj[v].z;
                float d2 = fmaf(dx, dx, fmaf(dy, dy, dz * dz));
                d2 = fmaxf(d2, 1.0486e-6f);
                float t = fminf(d2 * rsqrtf(d2), kClampT512);
                int it = (int)t;
                int lo = it >> 9;
                unsigned q = (unsigned)(it & 511);
                unsigned long long val =
                    ((unsigned long long)q << 32) | (unsigned long long)(512u - q);
                unsigned int* addr = (lo & 1) ? (baseB + lo + 1) : (baseA + lo);
                if (iu < jv)                                 // strict upper triangle
                    atomicAdd((unsigned long long*)addr, val);
            }
        }
    }
}

// ---------------------------------------------------------------------------
__global__ void finalize_kernel(float* __restrict__ out) {
    __shared__ double sh[256];
    const int tid = threadIdx.x;

    double h0 = 0.0, h1 = 0.0;
    if (tid < kNBins) {
        unsigned long long a0 = 0ull, a1 = 0ull;
#pragma unroll 8
        for (int r = 0; r < kReps; ++r) {
            a0 += (unsigned long long)g_rep[0][r].A[tid]
                + (unsigned long long)g_rep[0][r].B[tid + 1];
            a1 += (unsigned long long)g_rep[1][r].A[tid]
                + (unsigned long long)g_rep[1][r].B[tid + 1];
        }
        h0 = (double)a0;
        h1 = (double)a1;
    }

    sh[tid] = h0; __syncthreads();
    for (int o = 128; o > 0; o >>= 1) { if (tid < o) sh[tid] += sh[tid + o]; __syncthreads(); }
    double s0 = sh[0]; __syncthreads();

    sh[tid] = h1; __syncthreads();
    for (int o = 128; o > 0; o >>= 1) { if (tid < o) sh[tid] += sh[tid + o]; __syncthreads(); }
    double s1 = sh[0]; __syncthreads();

    double l = fabs(h0 / (s0 + 1e-12) - h1 / (s1 + 1e-12));
    sh[tid] = l; __syncthreads();
    for (int o = 128; o > 0; o >>= 1) { if (tid < o) sh[tid] += sh[tid + o]; __syncthreads(); }

    if (tid == 0) out[0] = (float)sh[0];
}

// ---------------------------------------------------------------------------
extern "C" void kernel_launch(void* const* d_in, const int* in_sizes, int n_in,
                              void* d_out, int out_size) {
    (void)in_sizes; (void)n_in; (void)out_size;
    const float* pred = (const float*)d_in[0];
    const float* tru  = (const float*)d_in[1];
    const float* mask = (const float*)d_in[2];

    zero_kernel<<<128, 256>>>();
    prepack_kernel<<<(kNAtoms + 255) / 256, 256>>>(pred, tru, mask);

    dim3 grid(kNPairTiles, 2);
    pair_hist_kernel<<<grid, 256>>>();

    finalize_kernel<<<1, 256>>>((float*)d_out);
}

// round 4
// speedup vs baseline: 2.5351x; 1.4701x over previous
#include <cuda_runtime.h>

// SAXS pair-distance P(r) L1 loss — Round 3.
// Change vs R2: DUAL-BACKEND histogram scatter. 3/8 of pairs go through
// per-block shared-memory 64-bit atomics (smem atomic ALU, 2 cyc/lane),
// 5/8 through global RED.E.ADD.64 into the 128x-replicated L2 histogram
// (L2 atomic ALU, 1.29 cyc/lane). The two ALUs are distinct backends ->
// additive throughput, ~0.81 cyc/pair vs 1.29 single-path.
// Parity-packed adjacent-bin trick retained on both paths (one u64 add
// carries both soft-bin fixed-point counts). Finalize parallelized 4x.

namespace {
constexpr int   kNBins      = 201;                       // DMAX/STEP + 1
constexpr int   kNAtoms     = 9472;                      // 256*37
constexpr int   kTile       = 128;
constexpr int   kNTiles     = kNAtoms / kTile;           // 74 (exact)
constexpr int   kNPairTiles = kNTiles * (kNTiles + 1) / 2;  // 2775
constexpr int   kReps       = 128;                       // histogram replicas
constexpr float kPre        = 1024.0f;                   // 512 / STEP
constexpr float kClampT512  = 103418.0f;                 // ~201.99*512 (lo<=201 discard)
}

struct Rep {
    unsigned int A[256];   // bin b total contribution at A[b]
    unsigned int B[256];   // bin b total contribution at B[b+1]
};

__device__ float4 g_pos[2][kNAtoms];   // prescaled (x,y,z,-), [0]=pred, [1]=true
__device__ Rep    g_rep[2][kReps];     // 512 KB, L2-resident

// ---------------------------------------------------------------------------
__global__ void zero_kernel() {
    uint4* p = (uint4*)g_rep;          // 2*128*512 u32 = 32768 uint4
    int i = blockIdx.x * blockDim.x + threadIdx.x;
    p[i] = make_uint4(0u, 0u, 0u, 0u);
}

// ---------------------------------------------------------------------------
__global__ void prepack_kernel(const float* __restrict__ pred,
                               const float* __restrict__ tru,
                               const float* __restrict__ mask) {
    int i = blockIdx.x * blockDim.x + threadIdx.x;
    if (i >= kNAtoms) return;
    float m = mask[i];
    if (m != 0.0f) {
        g_pos[0][i] = make_float4(pred[3*i+0]*kPre, pred[3*i+1]*kPre, pred[3*i+2]*kPre, 0.f);
        g_pos[1][i] = make_float4(tru [3*i+0]*kPre, tru [3*i+1]*kPre, tru [3*i+2]*kPre, 0.f);
    } else {
        // Displace masked atoms: every pair involving them exceeds the t clamp
        // -> lo=201 discard bin. (All separations among displaced atoms too.)
        float dx = 1.0e8f + (float)i * 2.0e5f;
        g_pos[0][i] = make_float4(dx, 0.f, 0.f, 0.f);
        g_pos[1][i] = make_float4(dx, 0.f, 0.f, 0.f);
    }
}

// ---------------------------------------------------------------------------
__global__ __launch_bounds__(256, 3)
void pair_hist_kernel() {
    __shared__ float4 ti[kTile];
    __shared__ float4 tj[kTile];
    __shared__ __align__(8) unsigned int shA[208];  // smem parity hist (even lo)
    __shared__ __align__(8) unsigned int shB[208];  // smem parity hist (odd  lo)

    const int s = blockIdx.y;          // 0 = pred, 1 = true
    const int p = blockIdx.x;          // linear upper-triangle tile index

    // Decode p -> (bi, bj), bi <= bj (row-major upper triangle incl. diagonal).
    double Td = (double)kNTiles;
    int bi = (int)(((2.0 * Td + 1.0) -
                    sqrt((2.0 * Td + 1.0) * (2.0 * Td + 1.0) - 8.0 * (double)p)) * 0.5);
    if (bi < 0) bi = 0;
    if (bi > kNTiles - 1) bi = kNTiles - 1;
    while (bi * (2 * kNTiles - bi + 1) / 2 > p) --bi;
    while ((bi + 1) * (2 * kNTiles - bi) / 2 <= p) ++bi;
    const int bj = bi + (p - bi * (2 * kNTiles - bi + 1) / 2);

    const int tid = threadIdx.x;
    if (tid < kTile) ti[tid]         = g_pos[s][bi * kTile + tid];
    else             tj[tid - kTile] = g_pos[s][bj * kTile + (tid - kTile)];
    for (int k = tid; k < 208; k += 256) { shA[k] = 0u; shB[k] = 0u; }
    __syncthreads();

    unsigned int* __restrict__ baseA = g_rep[s][p & (kReps - 1)].A;
    unsigned int* __restrict__ baseB = g_rep[s][p & (kReps - 1)].B;

    const int tx = tid & 15;           // 16x16 thread grid over 128x128 tile
    const int ty = tid >> 4;

    float3 ri[8], rj[8];
#pragma unroll
    for (int u = 0; u < 8; ++u) {
        float4 a = ti[ty * 8 + u];
        ri[u] = make_float3(a.x, a.y, a.z);
    }
#pragma unroll
    for (int v = 0; v < 8; ++v) {
        float4 b = tj[tx * 8 + v];
        rj[v] = make_float3(b.x, b.y, b.z);
    }

    const bool diag = (bi == bj);

#pragma unroll
    for (int u = 0; u < 8; ++u) {
        const int iu = ty * 8 + u;
#pragma unroll
        for (int v = 0; v < 8; ++v) {
            const int jv = tx * 8 + v;
            float dx = ri[u].x - rj[v].x;
            float dy = ri[u].y - rj[v].y;
            float dz = ri[u].z - rj[v].z;
            float d2 = fmaf(dx, dx, fmaf(dy, dy, dz * dz));
            d2 = fmaxf(d2, 1.0486e-6f);                  // 1e-12 * 1024^2
            float t = fminf(d2 * rsqrtf(d2), kClampT512);   // = d * 512/STEP
            int it = (int)t;
            int lo = it >> 9;
            unsigned q = (unsigned)(it & 511);
            unsigned long long val =
                ((unsigned long long)q << 32) | (unsigned long long)(512u - q);
            bool keep = !diag || (iu < jv);              // strict upper tri on diag
            if (v < 3) {                                 // compile-time split: smem
                unsigned int* addr = (lo & 1) ? (shB + lo + 1) : (shA + lo);
                if (keep) atomicAdd((unsigned long long*)addr, val);
            } else {                                     // global REDG
                unsigned int* addr = (lo & 1) ? (baseB + lo + 1) : (baseA + lo);
                if (keep) atomicAdd((unsigned long long*)addr, val);
            }
        }
    }

    __syncthreads();
    // Flush smem histogram: per-bin totals, pairs of bins packed into u64 REDG.
    // Bin b total (smem) = shA[b] + shB[b+1].
    if (tid < 101) {
        int b = 2 * tid;
        unsigned vlo = shA[b]     + shB[b + 1];
        unsigned vhi = shA[b + 1] + shB[b + 2];
        unsigned long long pv = ((unsigned long long)vhi << 32) | (unsigned long long)vlo;
        if (pv) atomicAdd((unsigned long long*)(baseA + b), pv);
    }
}

// ---------------------------------------------------------------------------
__global__ __launch_bounds__(1024)
void finalize_kernel(float* __restrict__ out) {
    __shared__ double part[2][4][256];    // 16 KB
    __shared__ double red[1024];          // 8 KB

    const int tid = threadIdx.x;
    const int b   = tid & 255;
    const int c   = tid >> 8;             // 0..3, rep-chunk

    unsigned long long a0 = 0ull, a1 = 0ull;
    if (b < kNBins) {
        const int r0 = c * 32;
#pragma unroll 4
        for (int r = r0; r < r0 + 32; ++r) {
            a0 += (unsigned long long)g_rep[0][r].A[b]
                + (unsigned long long)g_rep[0][r].B[b + 1];
            a1 += (unsigned long long)g_rep[1][r].A[b]
                + (unsigned long long)g_rep[1][r].B[b + 1];
        }
    }
    part[0][c][b] = (double)a0;
    part[1][c][b] = (double)a1;
    __syncthreads();

    double h0 = 0.0, h1 = 0.0;
    if (tid < 256) {
        h0 = part[0][0][tid] + part[0][1][tid] + part[0][2][tid] + part[0][3][tid];
        h1 = part[1][0][tid] + part[1][1][tid] + part[1][2][tid] + part[1][3][tid];
    }

    red[tid] = (tid < 256) ? h0 : 0.0; __syncthreads();
    for (int o = 512; o > 0; o >>= 1) { if (tid < o) red[tid] += red[tid + o]; __syncthreads(); }
    double s0 = red[0]; __syncthreads();

    red[tid] = (tid < 256) ? h1 : 0.0; __syncthreads();
    for (int o = 512; o > 0; o >>= 1) { if (tid < o) red[tid] += red[tid + o]; __syncthreads(); }
    double s1 = red[0]; __syncthreads();

    red[tid] = (tid < kNBins) ? fabs(h0 / (s0 + 1e-12) - h1 / (s1 + 1e-12)) : 0.0;
    __syncthreads();
    for (int o = 512; o > 0; o >>= 1) { if (tid < o) red[tid] += red[tid + o]; __syncthreads(); }

    if (tid == 0) out[0] = (float)red[0];
}

// ---------------------------------------------------------------------------
extern "C" void kernel_launch(void* const* d_in, const int* in_sizes, int n_in,
                              void* d_out, int out_size) {
    (void)in_sizes; (void)n_in; (void)out_size;
    const float* pred = (const float*)d_in[0];
    const float* tru  = (const float*)d_in[1];
    const float* mask = (const float*)d_in[2];

    zero_kernel<<<128, 256>>>();
    prepack_kernel<<<(kNAtoms + 255) / 256, 256>>>(pred, tru, mask);

    dim3 grid(kNPairTiles, 2);
    pair_hist_kernel<<<grid, 256>>>();

    finalize_kernel<<<1, 1024>>>((float*)d_out);
}

// round 5
// speedup vs baseline: 5.2906x; 2.0869x over previous
#include <cuda_runtime.h>

// SAXS P(r) L1 loss — Round 4: NO atomics on the hot path.
// Each of 128 threads per block owns a PRIVATE smem histogram, laid out
// word*512 + tid*4 (bank == tid&31 -> always conflict-free, race-free),
// updated with plain LDS+IADD+STS. Soft-bin pair (lo,lo+1) packs into one
// u32 as two u16 fields (scale 256): hist[lo] += (256-q) | (q<<16).
// Blocks are persistent over ~10 atom-tile pairs (grid 296 x 2 structures,
// 2 blocks/SM), double-buffered tile prefetch, one flush per block.

namespace {
constexpr int   kNBins      = 201;
constexpr int   kNAtoms     = 9472;                       // 256*37
constexpr int   kTile       = 128;
constexpr int   kNTiles     = kNAtoms / kTile;            // 74
constexpr int   kNPairTiles = kNTiles * (kNTiles + 1) / 2;   // 2775
constexpr int   kBlocksX    = 296;                        // tile stride per block
constexpr float kPre        = 512.0f;                     // 256 / STEP (STEP=0.5)
constexpr float kClampIT    = 51711.0f;                   // word<=201 (trash)
constexpr int   kWords      = 204;                        // 201 bins + trash + pad
constexpr int   kHistBytes  = kWords * 128 * 4;           // 104448
constexpr int   kSmemBytes  = kHistBytes + 2 * 256 * 16;  // + ping-pong tiles
}

__device__ float4       g_pos[2][kNAtoms];   // prescaled (x,y,z,-)
__device__ unsigned int g_hist[2][256];      // fixed-point (scale 256) totals

// ---------------------------------------------------------------------------
__global__ void prepack_kernel(const float* __restrict__ pred,
                               const float* __restrict__ tru,
                               const float* __restrict__ mask) {
    int i = blockIdx.x * blockDim.x + threadIdx.x;
    if (i < 512) ((unsigned int*)g_hist)[i] = 0u;
    if (i >= kNAtoms) return;
    float m = mask[i];
    if (m != 0.0f) {
        g_pos[0][i] = make_float4(pred[3*i+0]*kPre, pred[3*i+1]*kPre, pred[3*i+2]*kPre, 0.f);
        g_pos[1][i] = make_float4(tru [3*i+0]*kPre, tru [3*i+1]*kPre, tru [3*i+2]*kPre, 0.f);
    } else {
        // Displace masked atoms: all their pair distances exceed the clamp ->
        // trash word 201, excluded from flush.
        float dx = 1.0e8f + (float)i * 2.0e5f;
        g_pos[0][i] = make_float4(dx, 0.f, 0.f, 0.f);
        g_pos[1][i] = make_float4(dx, 0.f, 0.f, 0.f);
    }
}

// ---------------------------------------------------------------------------
__device__ __forceinline__ void decode_tile(int p, int& bi, int& bj) {
    double Td = (double)kNTiles;
    int b = (int)(((2.0 * Td + 1.0) -
                   sqrt((2.0 * Td + 1.0) * (2.0 * Td + 1.0) - 8.0 * (double)p)) * 0.5);
    if (b < 0) b = 0;
    if (b > kNTiles - 1) b = kNTiles - 1;
    while (b * (2 * kNTiles - b + 1) / 2 > p) --b;
    while ((b + 1) * (2 * kNTiles - b) / 2 <= p) ++b;
    bi = b;
    bj = b + (p - b * (2 * kNTiles - b + 1) / 2);
}

// ---------------------------------------------------------------------------
__global__ __launch_bounds__(128, 2)
void pair_hist_kernel() {
    extern __shared__ unsigned int smem[];
    unsigned int* hist = smem;                              // [204][128] u32
    float4* buf = (float4*)(smem + kWords * 128);           // [2][256] float4

    const int s   = blockIdx.y;
    const int tid = threadIdx.x;
    const int tx  = tid & 15;      // col group: cols tx*8 + v
    const int ty  = tid >> 4;      // row group: rows ty*16 + u

    // Zero private histograms (conflict-free columns).
#pragma unroll 4
    for (int w = 0; w < kWords; ++w) hist[(w << 7) + tid] = 0u;

    // Prefetch first tile pair.
    int p = blockIdx.x;
    int bi, bj;
    decode_tile(p, bi, bj);
    float4 a = g_pos[s][bi * kTile + tid];
    float4 b = g_pos[s][bj * kTile + tid];
    int cur = 0;
    buf[tid]       = a;
    buf[128 + tid] = b;
    __syncthreads();

    for (;;) {
        const int pn = p + kBlocksX;
        const bool havenext = (pn < kNPairTiles);
        float4 an, bn; int bin_ = 0, bjn = 0;
        if (havenext) {
            decode_tile(pn, bin_, bjn);
            an = g_pos[s][bin_ * kTile + tid];
            bn = g_pos[s][bjn * kTile + tid];
        }

        // ---- compute 16x8 register sub-tile of the 128x128 pair tile ----
        const float4* ti = buf + cur * 256;
        const float4* tj = ti + 128;
        float3 ri[16], rj[8];
#pragma unroll
        for (int u = 0; u < 16; ++u) {
            float4 t4 = ti[ty * 16 + u];
            ri[u] = make_float3(t4.x, t4.y, t4.z);
        }
#pragma unroll
        for (int v = 0; v < 8; ++v) {
            float4 t4 = tj[tx * 8 + v];
            rj[v] = make_float3(t4.x, t4.y, t4.z);
        }

        if (bi != bj) {
#pragma unroll
            for (int u = 0; u < 16; ++u) {
#pragma unroll
                for (int v = 0; v < 8; ++v) {
                    float dx = ri[u].x - rj[v].x;
                    float dy = ri[u].y - rj[v].y;
                    float dz = ri[u].z - rj[v].z;
                    float d2 = fmaf(dx, dx, fmaf(dy, dy, dz * dz));
                    d2 = fmaxf(d2, 2.62144e-7f);            // 1e-12 * 512^2
                    float t = fminf(d2 * rsqrtf(d2), kClampIT);  // d*256/STEP
                    int it = (int)t;
                    int word = it >> 8;
                    unsigned q = (unsigned)(it & 255);
                    unsigned val = (256u - q) + (q << 16);  // IMAD q,65535,256
                    hist[(word << 7) + tid] += val;         // private: no race
                }
            }
        } else {
#pragma unroll
            for (int u = 0; u < 16; ++u) {
                const int iu = ty * 16 + u;
#pragma unroll
                for (int v = 0; v < 8; ++v) {
                    const int jv = tx * 8 + v;
                    float dx = ri[u].x - rj[v].x;
                    float dy = ri[u].y - rj[v].y;
                    float dz = ri[u].z - rj[v].z;
                    float d2 = fmaf(dx, dx, fmaf(dy, dy, dz * dz));
                    d2 = fmaxf(d2, 2.62144e-7f);
                    float t = fminf(d2 * rsqrtf(d2), kClampIT);
                    int it = (int)t;
                    if (iu >= jv) it = 203 << 8;            // trash word
                    int word = it >> 8;
                    unsigned q = (unsigned)(it & 255);
                    unsigned val = (256u - q) + (q << 16);
                    hist[(word << 7) + tid] += val;
                }
            }
        }

        __syncthreads();
        if (!havenext) break;
        buf[(cur ^ 1) * 256 + tid]       = an;
        buf[(cur ^ 1) * 256 + 128 + tid] = bn;
        __syncthreads();
        cur ^= 1; p = pn; bi = bin_; bj = bjn;
    }

    // ---- flush: bin b total = sum_t low(hist[b][t]) + high(hist[b-1][t]) ----
    unsigned int* shh = (unsigned int*)buf;   // 204 u32 scratch
    unsigned slo_c[2];
#pragma unroll
    for (int c = 0; c < 2; ++c) {
        int w = tid + c * 128;
        unsigned slo = 0, shi = 0;
        if (w < kWords) {
            for (int i = 0; i < 128; ++i) {
                int t = (tid + i) & 127;                    // stagger: no conflicts
                unsigned v = hist[(w << 7) + t];
                slo += v & 0xFFFFu;
                shi += v >> 16;
            }
            shh[w] = shi;
        }
        slo_c[c] = slo;
    }
    __syncthreads();
#pragma unroll
    for (int c = 0; c < 2; ++c) {
        int w = tid + c * 128;
        if (w <= 200) {
            unsigned total = slo_c[c]
                           + (w > 0 ? shh[w - 1] : 0u)
                           + (w == 200 ? shh[200] : 0u);    // ref clips bin 201 -> 200
            if (total) atomicAdd(&g_hist[s][w], total);
        }
    }
}

// ---------------------------------------------------------------------------
__global__ void finalize_kernel(float* __restrict__ out) {
    __shared__ double sh[256];
    const int tid = threadIdx.x;
    double h0 = (tid < kNBins) ? (double)g_hist[0][tid] : 0.0;
    double h1 = (tid < kNBins) ? (double)g_hist[1][tid] : 0.0;

    sh[tid] = h0; __syncthreads();
    for (int o = 128; o > 0; o >>= 1) { if (tid < o) sh[tid] += sh[tid + o]; __syncthreads(); }
    double s0 = sh[0]; __syncthreads();

    sh[tid] = h1; __syncthreads();
    for (int o = 128; o > 0; o >>= 1) { if (tid < o) sh[tid] += sh[tid + o]; __syncthreads(); }
    double s1 = sh[0]; __syncthreads();

    sh[tid] = fabs(h0 / (s0 + 1e-12) - h1 / (s1 + 1e-12)); __syncthreads();
    for (int o = 128; o > 0; o >>= 1) { if (tid < o) sh[tid] += sh[tid + o]; __syncthreads(); }

    if (tid == 0) out[0] = (float)sh[0];
}

// ---------------------------------------------------------------------------
extern "C" void kernel_launch(void* const* d_in, const int* in_sizes, int n_in,
                              void* d_out, int out_size) {
    (void)in_sizes; (void)n_in; (void)out_size;
    const float* pred = (const float*)d_in[0];
    const float* tru  = (const float*)d_in[1];
    const float* mask = (const float*)d_in[2];

    cudaFuncSetAttribute(pair_hist_kernel,
                         cudaFuncAttributeMaxDynamicSharedMemorySize, kSmemBytes);

    prepack_kernel<<<(kNAtoms + 255) / 256, 256>>>(pred, tru, mask);

    dim3 grid(kBlocksX, 2);
    pair_hist_kernel<<<grid, 128, kSmemBytes>>>();

    finalize_kernel<<<1, 256>>>((float*)d_out);
}